// round 8
// baseline (speedup 1.0000x reference)
#include <cuda_runtime.h>
#include <cuda_bf16.h>
#include <math.h>
#include <stdint.h>

#define NB    32
#define HID   1024
#define TSTEP 63
#define ENCL  64
#define G3    3072
#define PADK  36
#define NBLK  296

#define DEC_HIDS_ELEMS (NB * TSTEP * HID)
#define ATTS_ELEMS     (NB * ENCL * TSTEP)
#define ATT_BASE       DEC_HIDS_ELEMS
#define DECPREV_BASE   (DEC_HIDS_ELEMS + ATTS_ELEMS)

// ---------------------------------------------------------------------------
// Scratch
// ---------------------------------------------------------------------------
__device__ float g_enc_proj[NB * ENCL * 1024];     // enc @ W_att_enc^T
__device__ float g_encW    [NB * ENCL * 1024];     // enc @ W_ctx^T
__device__ float g_emb_merged[TSTEP * NB * 1024];  // emb@W_in^T + b_in + b_ctx

__device__ float g_h[2 * NB * HID];
__device__ float g_merged[NB * HID];
__device__ float g_score[NB * ENCL];

__device__ float g_dp_part [4 * NB * HID];
__device__ float g_gh0_part[4 * NB * G3];
__device__ float g_gh1_part[4 * NB * G3];
__device__ float g_gi_part [4 * NB * G3];

__device__ unsigned g_bar_cnt;
__device__ unsigned g_bar_gen;

// ---------------------------------------------------------------------------
// Helpers
// ---------------------------------------------------------------------------
__device__ __forceinline__ float tanh_fast(float x) {
    float y;
    asm("tanh.approx.f32 %0, %1;" : "=f"(y) : "f"(x));
    return y;
}
__device__ __forceinline__ uint32_t f2tf(float x) {
    uint32_t r;
    asm("cvt.rna.tf32.f32 %0, %1;" : "=r"(r) : "f"(x));
    return r;
}
__device__ __forceinline__ void mma8(float* d, const uint32_t* a,
                                     uint32_t b0, uint32_t b1) {
    asm volatile(
        "mma.sync.aligned.m16n8k8.row.col.f32.tf32.tf32.f32 "
        "{%0,%1,%2,%3}, {%4,%5,%6,%7}, {%8,%9}, {%0,%1,%2,%3};"
        : "+f"(d[0]), "+f"(d[1]), "+f"(d[2]), "+f"(d[3])
        : "r"(a[0]), "r"(a[1]), "r"(a[2]), "r"(a[3]), "r"(b0), "r"(b1));
}
__device__ __forceinline__ void cp16(void* smem_dst, const void* gsrc) {
    unsigned s = (unsigned)__cvta_generic_to_shared(smem_dst);
    asm volatile("cp.async.ca.shared.global [%0], [%1], 16;" :: "r"(s), "l"(gsrc));
}
__device__ __forceinline__ void cp_commit() {
    asm volatile("cp.async.commit_group;");
}
template<int N> __device__ __forceinline__ void cp_wait() {
    asm volatile("cp.async.wait_group %0;" :: "n"(N));
}

// Grid-wide barrier. All NBLK blocks resident (2/SM guaranteed) -> no deadlock.
__device__ __forceinline__ void gridbar() {
    __threadfence();            // publish this block's writes
    __syncthreads();
    if (threadIdx.x == 0) {
        unsigned my = *(volatile unsigned*)&g_bar_gen;
        unsigned old = atomicAdd(&g_bar_cnt, 1u);
        if (old == NBLK - 1) {
            atomicExch(&g_bar_cnt, 0u);
            __threadfence();
            atomicAdd(&g_bar_gen, 1u);
        } else {
            while (*(volatile unsigned*)&g_bar_gen == my) { }
        }
    }
    __syncthreads();
    __threadfence();            // invalidate L1 before consuming others' writes
}

// ---------------------------------------------------------------------------
// tf32 tc GEMM: out[32 x 128cols @j0] = A[32 x 256k @k0] @ W^T (W: [C][1024])
// 128 threads / 4 warps; smem passed in (2304 + 9216 floats).
// ---------------------------------------------------------------------------
__device__ __forceinline__ void stage_chunk(float* Asb, float* Wsb,
                                            const float* __restrict__ A,
                                            const float* __restrict__ W,
                                            int j0, int kg, int tid) {
#pragma unroll
    for (int i = 0; i < 2; i++) {
        int idx = tid + i * 128;
        int row = idx >> 3, seg = idx & 7;
        cp16(Asb + row * PADK + seg * 4, A + (size_t)row * 1024 + kg + seg * 4);
    }
#pragma unroll
    for (int i = 0; i < 8; i++) {
        int idx = tid + i * 128;
        int row = idx >> 3, seg = idx & 7;
        cp16(Wsb + row * PADK + seg * 4, W + (size_t)(j0 + row) * 1024 + kg + seg * 4);
    }
    cp_commit();
}

__device__ __forceinline__ void gemm_tc(const float* __restrict__ A,
                                        const float* __restrict__ W,
                                        int C, int j0, int k0,
                                        float* __restrict__ outp,
                                        float* sm) {
    float* As0 = sm;                  // 32*PADK = 1152
    float* As1 = sm + 1152;
    float* Ws0 = sm + 2304;           // 128*PADK = 4608
    float* Ws1 = sm + 2304 + 4608;
    int tid = threadIdx.x;
    int wid = tid >> 5, lane = tid & 31;
    int r = lane >> 2, q = lane & 3;

    stage_chunk(As0, Ws0, A, W, j0, k0, tid);
    stage_chunk(As1, Ws1, A, W, j0, k0 + 32, tid);

    float acc[2][4][4];
#pragma unroll
    for (int mt = 0; mt < 2; mt++)
#pragma unroll
        for (int nt = 0; nt < 4; nt++)
#pragma unroll
            for (int i = 0; i < 4; i++) acc[mt][nt][i] = 0.f;

#pragma unroll
    for (int c = 0; c < 8; c++) {
        if (c + 1 < 8) cp_wait<1>(); else cp_wait<0>();
        __syncthreads();
        const float* as = (c & 1) ? As1 : As0;
        const float* ws = (c & 1) ? Ws1 : Ws0;
#pragma unroll
        for (int ks = 0; ks < 4; ks++) {
            int kq = ks * 8 + q;
            uint32_t afr[2][4];
#pragma unroll
            for (int mt = 0; mt < 2; mt++) {
                afr[mt][0] = f2tf(as[(mt * 16 + r)     * PADK + kq]);
                afr[mt][1] = f2tf(as[(mt * 16 + r + 8) * PADK + kq]);
                afr[mt][2] = f2tf(as[(mt * 16 + r)     * PADK + kq + 4]);
                afr[mt][3] = f2tf(as[(mt * 16 + r + 8) * PADK + kq + 4]);
            }
#pragma unroll
            for (int nt = 0; nt < 4; nt++) {
                int n = wid * 32 + nt * 8 + r;
                uint32_t b0 = f2tf(ws[n * PADK + ks * 8 + q]);
                uint32_t b1 = f2tf(ws[n * PADK + ks * 8 + 4 + q]);
                mma8(acc[0][nt], afr[0], b0, b1);
                mma8(acc[1][nt], afr[1], b0, b1);
            }
        }
        if (c + 2 < 8) {
            __syncthreads();
            stage_chunk((c & 1) ? As1 : As0, (c & 1) ? Ws1 : Ws0,
                        A, W, j0, k0 + (c + 2) * 32, tid);
        }
    }
#pragma unroll
    for (int mt = 0; mt < 2; mt++) {
#pragma unroll
        for (int nt = 0; nt < 4; nt++) {
            int col = j0 + wid * 32 + nt * 8 + 2 * q;
            int row0 = mt * 16 + r;
            *(float2*)(outp + (size_t)row0 * C + col) =
                make_float2(acc[mt][nt][0], acc[mt][nt][1]);
            *(float2*)(outp + (size_t)(row0 + 8) * C + col) =
                make_float2(acc[mt][nt][2], acc[mt][nt][3]);
        }
    }
}

// ---------------------------------------------------------------------------
// Phase bodies
// ---------------------------------------------------------------------------
__device__ __forceinline__ void score_body(const float* __restrict__ v_att,
                                           float* sm, int b) {
    float* sdec = sm;
    float* sv   = sm + 1024;
    int n = b >> 3, lg = b & 7;
    int tid = threadIdx.x;
    for (int i = tid; i < 1024; i += 128) {
        sdec[i] = g_dp_part[n * 1024 + i]
                + g_dp_part[(NB + n) * 1024 + i]
                + g_dp_part[(2 * NB + n) * 1024 + i]
                + g_dp_part[(3 * NB + n) * 1024 + i];
        sv[i] = v_att[i];
    }
    __syncthreads();
    int w = tid >> 5, lane = tid & 31;
#pragma unroll
    for (int li = 0; li < 2; li++) {
        int l = lg * 8 + w * 2 + li;
        const float* ep = g_enc_proj + ((size_t)n * 64 + l) * 1024;
        float s = 0.f;
        for (int a = lane; a < 1024; a += 32)
            s += tanh_fast(ep[a] + sdec[a]) * sv[a];
#pragma unroll
        for (int o = 16; o; o >>= 1) s += __shfl_xor_sync(0xffffffffu, s, o);
        if (lane == 0) g_score[n * 64 + l] = s;
    }
}

__device__ __forceinline__ void softmerge_body(int n, int t,
                                               float* __restrict__ out,
                                               float* sm) {
    float* satt = sm;   // 64 floats
    int tid = threadIdx.x;
    if (tid < 32) {
        float a0 = g_score[n * 64 + tid], a1 = g_score[n * 64 + tid + 32];
        float m = fmaxf(a0, a1);
#pragma unroll
        for (int o = 16; o; o >>= 1) m = fmaxf(m, __shfl_xor_sync(0xffffffffu, m, o));
        float e0 = __expf(a0 - m), e1 = __expf(a1 - m);
        float sum = e0 + e1;
#pragma unroll
        for (int o = 16; o; o >>= 1) sum += __shfl_xor_sync(0xffffffffu, sum, o);
        float inv = 1.f / sum;
        satt[tid]      = e0 * inv;
        satt[tid + 32] = e1 * inv;
        out[ATT_BASE + ((size_t)n * 64 + tid)      * TSTEP + t] = e0 * inv;
        out[ATT_BASE + ((size_t)n * 64 + tid + 32) * TSTEP + t] = e1 * inv;
    }
    __syncthreads();
    const float* em = g_emb_merged + ((size_t)t * NB + n) * 1024;
    const float* ew = g_encW + (size_t)n * 64 * 1024;
#pragma unroll
    for (int half = 0; half < 2; half++) {
        int d = (tid + half * 128) * 4;
        float4 acc = *(const float4*)(em + d);
#pragma unroll 8
        for (int l = 0; l < 64; l++) {
            float  al = satt[l];
            float4 e  = *(const float4*)(ew + (size_t)l * 1024 + d);
            acc.x += al * e.x; acc.y += al * e.y;
            acc.z += al * e.z; acc.w += al * e.w;
        }
        *(float4*)&g_merged[n * 1024 + d] = acc;
    }
}

__device__ __forceinline__ void add4(float* a, float4 v) {
    a[0] += v.x; a[1] += v.y; a[2] += v.z; a[3] += v.w;
}

__device__ __forceinline__ void combine_body(int layer, int t, int n,
                                             const float* __restrict__ b_ih_l,
                                             const float* __restrict__ b_hh_l,
                                             float* __restrict__ out_hid) {
    int tid = threadIdx.x;
    const float* ghp = layer ? g_gh1_part : g_gh0_part;
    float* h = g_h + (size_t)layer * NB * HID + n * HID;
#pragma unroll
    for (int half = 0; half < 2; half++) {
        int j = tid * 4 + half * 512;
        float gi[3][4] = {}, gh[3][4] = {};
#pragma unroll
        for (int g = 0; g < 3; g++) {
#pragma unroll
            for (int s = 0; s < 4; s++) {
                add4(gi[g], *(const float4*)(g_gi_part + ((size_t)s * NB + n) * G3 + g * 1024 + j));
                add4(gh[g], *(const float4*)(ghp       + ((size_t)s * NB + n) * G3 + g * 1024 + j));
            }
            add4(gi[g], *(const float4*)(b_ih_l + g * 1024 + j));
            add4(gh[g], *(const float4*)(b_hh_l + g * 1024 + j));
        }
        float4 ho = *(const float4*)(h + j);
        float ho_[4] = {ho.x, ho.y, ho.z, ho.w};
        float hn_[4];
#pragma unroll
        for (int c = 0; c < 4; c++) {
            float r  = 1.f / (1.f + expf(-(gi[0][c] + gh[0][c])));
            float z  = 1.f / (1.f + expf(-(gi[1][c] + gh[1][c])));
            float nn = tanhf(gi[2][c] + r * gh[2][c]);
            hn_[c] = (1.f - z) * nn + z * ho_[c];
        }
        float4 hv = {hn_[0], hn_[1], hn_[2], hn_[3]};
        *(float4*)(h + j) = hv;
        if (out_hid)
            *(float4*)(out_hid + ((size_t)n * TSTEP + t) * 1024 + j) = hv;
    }
}

// ---------------------------------------------------------------------------
// Persistent decode kernel: all 63 steps, 7 grid barriers per step
// ---------------------------------------------------------------------------
__global__ void __launch_bounds__(128) decode_kernel(
        const float* __restrict__ dec_init,
        const float* __restrict__ W_att_dec,
        const float* __restrict__ W_hh,
        const float* __restrict__ W_ih,
        const float* __restrict__ b_ih,
        const float* __restrict__ b_hh,
        const float* __restrict__ v_att,
        float* __restrict__ out) {
    __shared__ float sm[11520];   // 46080 B
    int b = blockIdx.x;
    int tid = threadIdx.x;

    // init h from dec_init
    for (int i = b * 128 + tid; i < 2 * NB * HID; i += NBLK * 128)
        g_h[i] = dec_init[i];
    gridbar();

    for (int t = 0; t < TSTEP; t++) {
        // phase A: dp(32) + gh0(96) + gh1(96)
        if (b < 32) {
            int tile = b >> 2, split = b & 3;
            gemm_tc(g_h + NB * HID, W_att_dec, 1024, tile * 128, split * 256,
                    g_dp_part + (size_t)split * NB * 1024, sm);
        } else if (b < 128) {
            int x = b - 32; int tile = x >> 2, split = x & 3;
            gemm_tc(g_h, W_hh, G3, tile * 128, split * 256,
                    g_gh0_part + (size_t)split * NB * G3, sm);
        } else if (b < 224) {
            int x = b - 128; int tile = x >> 2, split = x & 3;
            gemm_tc(g_h + NB * HID, W_hh + (size_t)G3 * 1024, G3, tile * 128,
                    split * 256, g_gh1_part + (size_t)split * NB * G3, sm);
        }
        gridbar();

        // score
        if (b < 256) score_body(v_att, sm, b);
        gridbar();

        // softmax + atts + merged (fp32)
        if (b < 32) softmerge_body(b, t, out, sm);
        gridbar();

        // gi layer 0
        if (b < 96) {
            int tile = b >> 2, split = b & 3;
            gemm_tc(g_merged, W_ih, G3, tile * 128, split * 256,
                    g_gi_part + (size_t)split * NB * G3, sm);
        }
        gridbar();

        // combine layer 0
        if (b < 32) combine_body(0, t, b, b_ih, b_hh, nullptr);
        gridbar();

        // gi layer 1
        if (b < 96) {
            int tile = b >> 2, split = b & 3;
            gemm_tc(g_h, W_ih + (size_t)G3 * 1024, G3, tile * 128, split * 256,
                    g_gi_part + (size_t)split * NB * G3, sm);
        }
        gridbar();

        // combine layer 1 (+ dec_hids output)
        if (b < 32) combine_body(1, t, b, b_ih + G3, b_hh + G3, out);
        gridbar();
    }

    // epilogue: dec_prev
    for (int i = b * 128 + tid; i < 2 * NB * HID; i += NBLK * 128)
        out[DECPREV_BASE + i] = g_h[i];
}

// ---------------------------------------------------------------------------
// Prologue: 3 fused fp32 GEMMs (enc_proj, emb_merged, encW) + barrier reset
// 1536 blocks x 256 threads; 64x64 tiles, K=1024
// ---------------------------------------------------------------------------
__global__ void prol_gemm_kernel(const float* __restrict__ enc_hids,
                                 const int*   __restrict__ input_ids,
                                 const float* __restrict__ emb_table,
                                 const float* __restrict__ b_in,
                                 const float* __restrict__ b_ctx,
                                 const float* __restrict__ W_att_enc,
                                 const float* __restrict__ W_in,
                                 const float* __restrict__ W_ctx) {
    if (blockIdx.x == 0 && threadIdx.x == 0) {
        g_bar_cnt = 0;
        g_bar_gen = 0;
    }
    __shared__ float As[2][32 * 68];
    __shared__ float Ws[2][32 * 68];
    int mode = blockIdx.x >> 9;
    int b = blockIdx.x & 511;
    int rt = b >> 4, ct = b & 15;
    int r0 = rt * 64, c0 = ct * 64;
    int tid = threadIdx.x;
    int lp = tid & 7, lr = tid >> 3;
    int tx = tid & 15, ty = tid >> 4;
    int rows = (mode == 1) ? (TSTEP * NB) : 2048;
    const float* W = (mode == 0) ? W_att_enc : ((mode == 1) ? W_in : W_ctx);

    float4 a[2], wv[2];
#define PROL_FETCH(k0)                                                          \
    {                                                                           \
        _Pragma("unroll")                                                       \
        for (int h = 0; h < 2; h++) {                                           \
            int gr = r0 + lr + h * 32;                                          \
            if (mode != 1) {                                                    \
                a[h] = *(const float4*)(enc_hids + (size_t)gr * 1024 + (k0) + lp * 4); \
            } else if (gr < rows) {                                             \
                int id = input_ids[(gr & 31) * 64 + (gr >> 5)];                 \
                a[h] = *(const float4*)(emb_table + (size_t)id * 1024 + (k0) + lp * 4); \
            } else {                                                            \
                a[h] = make_float4(0.f, 0.f, 0.f, 0.f);                         \
            }                                                                   \
            wv[h] = *(const float4*)(W + (size_t)(c0 + lr + h * 32) * 1024 + (k0) + lp * 4); \
        }                                                                       \
    }
#define PROL_STORE(buf)                                                         \
    {                                                                           \
        _Pragma("unroll")                                                       \
        for (int h = 0; h < 2; h++) {                                           \
            int rr = lr + h * 32;                                               \
            As[buf][(lp * 4 + 0) * 68 + rr] = a[h].x;                           \
            As[buf][(lp * 4 + 1) * 68 + rr] = a[h].y;                           \
            As[buf][(lp * 4 + 2) * 68 + rr] = a[h].z;                           \
            As[buf][(lp * 4 + 3) * 68 + rr] = a[h].w;                           \
            Ws[buf][(lp * 4 + 0) * 68 + rr] = wv[h].x;                          \
            Ws[buf][(lp * 4 + 1) * 68 + rr] = wv[h].y;                          \
            Ws[buf][(lp * 4 + 2) * 68 + rr] = wv[h].z;                          \
            Ws[buf][(lp * 4 + 3) * 68 + rr] = wv[h].w;                          \
        }                                                                       \
    }

    float acc[4][4];
#pragma unroll
    for (int i = 0; i < 4; i++)
#pragma unroll
        for (int j = 0; j < 4; j++) acc[i][j] = 0.f;

    PROL_FETCH(0);
    PROL_STORE(0);
    __syncthreads();
    for (int c = 0; c < 32; c++) {
        const float* as = As[c & 1];
        const float* ws = Ws[c & 1];
        if (c + 1 < 32) PROL_FETCH((c + 1) * 32);
#pragma unroll
        for (int kk = 0; kk < 32; kk++) {
            float4 a4 = *(const float4*)&as[kk * 68 + ty * 4];
            float4 b4 = *(const float4*)&ws[kk * 68 + tx * 4];
            float avv[4] = {a4.x, a4.y, a4.z, a4.w};
            float bvv[4] = {b4.x, b4.y, b4.z, b4.w};
#pragma unroll
            for (int i = 0; i < 4; i++)
#pragma unroll
                for (int j = 0; j < 4; j++) acc[i][j] += avv[i] * bvv[j];
        }
        if (c + 1 < 32) {
            PROL_STORE((c + 1) & 1);
            __syncthreads();
        }
    }
    float* outb = (mode == 0) ? g_enc_proj : ((mode == 1) ? g_emb_merged : g_encW);
#pragma unroll
    for (int i = 0; i < 4; i++) {
        int rr = r0 + ty * 4 + i;
        if (rr >= rows) continue;
#pragma unroll
        for (int j = 0; j < 4; j++) {
            int cc = c0 + tx * 4 + j;
            float bias = (mode == 1) ? (b_in[cc] + b_ctx[cc]) : 0.f;
            outb[(size_t)rr * 1024 + cc] = acc[i][j] + bias;
        }
    }
#undef PROL_FETCH
#undef PROL_STORE
}

// ---------------------------------------------------------------------------
extern "C" void kernel_launch(void* const* d_in, const int* in_sizes, int n_in,
                              void* d_out, int out_size) {
    const int*   input_ids = (const int*)  d_in[0];
    const float* dec_init  = (const float*)d_in[1];
    const float* enc_hids  = (const float*)d_in[2];
    const float* emb_table = (const float*)d_in[3];
    const float* W_in      = (const float*)d_in[4];
    const float* b_in      = (const float*)d_in[5];
    const float* W_ctx     = (const float*)d_in[6];
    const float* b_ctx     = (const float*)d_in[7];
    const float* W_att_dec = (const float*)d_in[8];
    const float* W_att_enc = (const float*)d_in[9];
    const float* v_att     = (const float*)d_in[10];
    const float* W_ih      = (const float*)d_in[11];
    const float* W_hh      = (const float*)d_in[12];
    const float* b_ih      = (const float*)d_in[13];
    const float* b_hh      = (const float*)d_in[14];
    float* out = (float*)d_out;

    prol_gemm_kernel<<<1536, 256>>>(enc_hids, input_ids, emb_table,
                                    b_in, b_ctx, W_att_enc, W_in, W_ctx);
    decode_kernel<<<NBLK, 128>>>(dec_init, W_att_dec, W_hh, W_ih,
                                 b_ih, b_hh, v_att, out);
}

// round 9
// speedup vs baseline: 1.1159x; 1.1159x over previous
#include <cuda_runtime.h>
#include <cuda_bf16.h>
#include <math.h>
#include <stdint.h>

#define NB    32
#define HID   1024
#define TSTEP 63
#define ENCL  64
#define G3    3072
#define PADK  36
#define NBLK  224

#define DEC_HIDS_ELEMS (NB * TSTEP * HID)
#define ATTS_ELEMS     (NB * ENCL * TSTEP)
#define ATT_BASE       DEC_HIDS_ELEMS
#define DECPREV_BASE   (DEC_HIDS_ELEMS + ATTS_ELEMS)

// ---------------------------------------------------------------------------
// Scratch
// ---------------------------------------------------------------------------
__device__ float g_enc_proj[NB * ENCL * 1024];     // enc @ W_att_enc^T
__device__ float g_encW    [NB * ENCL * 1024];     // enc @ W_ctx^T
__device__ float g_emb_merged[TSTEP * NB * 1024];  // emb@W_in^T + b_in + b_ctx

__device__ float g_h[2 * NB * HID];
__device__ float g_merged[NB * HID];

__device__ float g_dp_part [4 * NB * HID];
__device__ float g_gh0_part[4 * NB * G3];
__device__ float g_gh1_part[4 * NB * G3];
__device__ float g_gi_part [8 * NB * G3];

__device__ unsigned g_bar_cnt;
__device__ unsigned g_bar_gen;

// ---------------------------------------------------------------------------
// Helpers
// ---------------------------------------------------------------------------
__device__ __forceinline__ float tanh_fast(float x) {
    float y;
    asm("tanh.approx.f32 %0, %1;" : "=f"(y) : "f"(x));
    return y;
}
__device__ __forceinline__ uint32_t f2tf(float x) {
    uint32_t r;
    asm("cvt.rna.tf32.f32 %0, %1;" : "=r"(r) : "f"(x));
    return r;
}
__device__ __forceinline__ void mma8(float* d, const uint32_t* a,
                                     uint32_t b0, uint32_t b1) {
    asm volatile(
        "mma.sync.aligned.m16n8k8.row.col.f32.tf32.tf32.f32 "
        "{%0,%1,%2,%3}, {%4,%5,%6,%7}, {%8,%9}, {%0,%1,%2,%3};"
        : "+f"(d[0]), "+f"(d[1]), "+f"(d[2]), "+f"(d[3])
        : "r"(a[0]), "r"(a[1]), "r"(a[2]), "r"(a[3]), "r"(b0), "r"(b1));
}
__device__ __forceinline__ void cp16(void* smem_dst, const void* gsrc) {
    unsigned s = (unsigned)__cvta_generic_to_shared(smem_dst);
    asm volatile("cp.async.ca.shared.global [%0], [%1], 16;" :: "r"(s), "l"(gsrc));
}
__device__ __forceinline__ void cp_commit() {
    asm volatile("cp.async.commit_group;");
}
template<int N> __device__ __forceinline__ void cp_wait() {
    asm volatile("cp.async.wait_group %0;" :: "n"(N));
}

// CG-style grid barrier: release-arrive + acquire-spin. All NBLK resident.
__device__ __forceinline__ void gridbar() {
    __syncthreads();
    if (threadIdx.x == 0) {
        unsigned* cnt = &g_bar_cnt;
        unsigned* gen = &g_bar_gen;
        unsigned my;
        asm volatile("ld.relaxed.gpu.u32 %0, [%1];" : "=r"(my) : "l"(gen));
        unsigned old;
        asm volatile("atom.add.acq_rel.gpu.u32 %0, [%1], 1;"
                     : "=r"(old) : "l"(cnt) : "memory");
        if (old == NBLK - 1) {
            asm volatile("st.relaxed.gpu.u32 [%0], %1;" :: "l"(cnt), "r"(0u) : "memory");
            asm volatile("red.release.gpu.add.u32 [%0], %1;" :: "l"(gen), "r"(1u) : "memory");
        } else {
            unsigned g;
            do {
                asm volatile("ld.acquire.gpu.u32 %0, [%1];"
                             : "=r"(g) : "l"(gen) : "memory");
            } while (g == my);
        }
    }
    __syncthreads();
}

// ---------------------------------------------------------------------------
// tf32 tc GEMM: out[32 x 128cols @j0] = A[32 x (NCH*32)k @k0] @ W^T
// W: [C][1024] fp32 native layout (.col B). 128 threads / 4 warps.
// ---------------------------------------------------------------------------
__device__ __forceinline__ void stage_chunk(float* Asb, float* Wsb,
                                            const float* __restrict__ A,
                                            const float* __restrict__ W,
                                            int j0, int kg, int tid) {
#pragma unroll
    for (int i = 0; i < 2; i++) {
        int idx = tid + i * 128;
        int row = idx >> 3, seg = idx & 7;
        cp16(Asb + row * PADK + seg * 4, A + (size_t)row * 1024 + kg + seg * 4);
    }
#pragma unroll
    for (int i = 0; i < 8; i++) {
        int idx = tid + i * 128;
        int row = idx >> 3, seg = idx & 7;
        cp16(Wsb + row * PADK + seg * 4, W + (size_t)(j0 + row) * 1024 + kg + seg * 4);
    }
    cp_commit();
}

template<int NCH>
__device__ __forceinline__ void gemm_tc(const float* __restrict__ A,
                                        const float* __restrict__ W,
                                        int C, int j0, int k0,
                                        float* __restrict__ outp,
                                        float* sm) {
    float* As0 = sm;
    float* As1 = sm + 1152;
    float* Ws0 = sm + 2304;
    float* Ws1 = sm + 2304 + 4608;
    int tid = threadIdx.x;
    int wid = tid >> 5, lane = tid & 31;
    int r = lane >> 2, q = lane & 3;

    stage_chunk(As0, Ws0, A, W, j0, k0, tid);
    stage_chunk(As1, Ws1, A, W, j0, k0 + 32, tid);

    float acc[2][4][4];
#pragma unroll
    for (int mt = 0; mt < 2; mt++)
#pragma unroll
        for (int nt = 0; nt < 4; nt++)
#pragma unroll
            for (int i = 0; i < 4; i++) acc[mt][nt][i] = 0.f;

#pragma unroll
    for (int c = 0; c < NCH; c++) {
        if (c + 1 < NCH) cp_wait<1>(); else cp_wait<0>();
        __syncthreads();
        const float* as = (c & 1) ? As1 : As0;
        const float* ws = (c & 1) ? Ws1 : Ws0;
#pragma unroll
        for (int ks = 0; ks < 4; ks++) {
            int kq = ks * 8 + q;
            uint32_t afr[2][4];
#pragma unroll
            for (int mt = 0; mt < 2; mt++) {
                afr[mt][0] = f2tf(as[(mt * 16 + r)     * PADK + kq]);
                afr[mt][1] = f2tf(as[(mt * 16 + r + 8) * PADK + kq]);
                afr[mt][2] = f2tf(as[(mt * 16 + r)     * PADK + kq + 4]);
                afr[mt][3] = f2tf(as[(mt * 16 + r + 8) * PADK + kq + 4]);
            }
#pragma unroll
            for (int nt = 0; nt < 4; nt++) {
                int n = wid * 32 + nt * 8 + r;
                uint32_t b0 = f2tf(ws[n * PADK + ks * 8 + q]);
                uint32_t b1 = f2tf(ws[n * PADK + ks * 8 + 4 + q]);
                mma8(acc[0][nt], afr[0], b0, b1);
                mma8(acc[1][nt], afr[1], b0, b1);
            }
        }
        if (c + 2 < NCH) {
            __syncthreads();
            stage_chunk((c & 1) ? As1 : As0, (c & 1) ? Ws1 : Ws0,
                        A, W, j0, k0 + (c + 2) * 32, tid);
        }
    }
#pragma unroll
    for (int mt = 0; mt < 2; mt++) {
#pragma unroll
        for (int nt = 0; nt < 4; nt++) {
            int col = j0 + wid * 32 + nt * 8 + 2 * q;
            int row0 = mt * 16 + r;
            *(float2*)(outp + (size_t)row0 * C + col) =
                make_float2(acc[mt][nt][0], acc[mt][nt][1]);
            *(float2*)(outp + (size_t)(row0 + 8) * C + col) =
                make_float2(acc[mt][nt][2], acc[mt][nt][3]);
        }
    }
}

// ---------------------------------------------------------------------------
// Fused attention phase body (one block per n):
// score (tanh) -> softmax (+atts out) -> merged = emb_merged[t] + att @ encW
// ---------------------------------------------------------------------------
__device__ __forceinline__ void attn_body(int n, int t,
                                          const float* __restrict__ v_att,
                                          float* __restrict__ out,
                                          float* sm) {
    float* sdec = sm;
    float* sv   = sm + 1024;
    float* ss   = sm + 2048;   // 64 scores -> att
    int tid = threadIdx.x;
    for (int i = tid; i < 1024; i += 128) {
        sdec[i] = g_dp_part[n * 1024 + i]
                + g_dp_part[(NB + n) * 1024 + i]
                + g_dp_part[(2 * NB + n) * 1024 + i]
                + g_dp_part[(3 * NB + n) * 1024 + i];
        sv[i] = v_att[i];
    }
    __syncthreads();
    int w = tid >> 5, lane = tid & 31;
#pragma unroll
    for (int li = 0; li < 16; li++) {
        int l = w * 16 + li;
        const float* ep = g_enc_proj + ((size_t)n * 64 + l) * 1024;
        float s = 0.f;
        for (int a = lane; a < 1024; a += 32)
            s += tanh_fast(ep[a] + sdec[a]) * sv[a];
#pragma unroll
        for (int o = 16; o; o >>= 1) s += __shfl_xor_sync(0xffffffffu, s, o);
        if (lane == 0) ss[l] = s;
    }
    __syncthreads();
    if (tid < 32) {
        float a0 = ss[tid], a1 = ss[tid + 32];
        float m = fmaxf(a0, a1);
#pragma unroll
        for (int o = 16; o; o >>= 1) m = fmaxf(m, __shfl_xor_sync(0xffffffffu, m, o));
        float e0 = __expf(a0 - m), e1 = __expf(a1 - m);
        float sum = e0 + e1;
#pragma unroll
        for (int o = 16; o; o >>= 1) sum += __shfl_xor_sync(0xffffffffu, sum, o);
        float inv = 1.f / sum;
        ss[tid]      = e0 * inv;
        ss[tid + 32] = e1 * inv;
        out[ATT_BASE + ((size_t)n * 64 + tid)      * TSTEP + t] = e0 * inv;
        out[ATT_BASE + ((size_t)n * 64 + tid + 32) * TSTEP + t] = e1 * inv;
    }
    __syncthreads();
    const float* em = g_emb_merged + ((size_t)t * NB + n) * 1024;
    const float* ew = g_encW + (size_t)n * 64 * 1024;
#pragma unroll
    for (int half = 0; half < 2; half++) {
        int d = (tid + half * 128) * 4;
        float4 acc = *(const float4*)(em + d);
#pragma unroll 8
        for (int l = 0; l < 64; l++) {
            float  al = ss[l];
            float4 e  = *(const float4*)(ew + (size_t)l * 1024 + d);
            acc.x += al * e.x; acc.y += al * e.y;
            acc.z += al * e.z; acc.w += al * e.w;
        }
        *(float4*)&g_merged[n * 1024 + d] = acc;
    }
}

// ---------------------------------------------------------------------------
// GRU combine: 8 gi splits + 4 gh splits + biases
// ---------------------------------------------------------------------------
__device__ __forceinline__ void add4(float* a, float4 v) {
    a[0] += v.x; a[1] += v.y; a[2] += v.z; a[3] += v.w;
}

__device__ __forceinline__ void combine_body(int layer, int t, int n,
                                             const float* __restrict__ b_ih_l,
                                             const float* __restrict__ b_hh_l,
                                             float* __restrict__ out_hid) {
    int tid = threadIdx.x;
    const float* ghp = layer ? g_gh1_part : g_gh0_part;
    float* h = g_h + (size_t)layer * NB * HID + n * HID;
#pragma unroll
    for (int half = 0; half < 2; half++) {
        int j = tid * 4 + half * 512;
        float gi[3][4] = {}, gh[3][4] = {};
#pragma unroll
        for (int g = 0; g < 3; g++) {
#pragma unroll
            for (int s = 0; s < 8; s++)
                add4(gi[g], *(const float4*)(g_gi_part + ((size_t)s * NB + n) * G3 + g * 1024 + j));
#pragma unroll
            for (int s = 0; s < 4; s++)
                add4(gh[g], *(const float4*)(ghp + ((size_t)s * NB + n) * G3 + g * 1024 + j));
            add4(gi[g], *(const float4*)(b_ih_l + g * 1024 + j));
            add4(gh[g], *(const float4*)(b_hh_l + g * 1024 + j));
        }
        float4 ho = *(const float4*)(h + j);
        float ho_[4] = {ho.x, ho.y, ho.z, ho.w};
        float hn_[4];
#pragma unroll
        for (int c = 0; c < 4; c++) {
            float r  = 1.f / (1.f + expf(-(gi[0][c] + gh[0][c])));
            float z  = 1.f / (1.f + expf(-(gi[1][c] + gh[1][c])));
            float nn = tanhf(gi[2][c] + r * gh[2][c]);
            hn_[c] = (1.f - z) * nn + z * ho_[c];
        }
        float4 hv = {hn_[0], hn_[1], hn_[2], hn_[3]};
        *(float4*)(h + j) = hv;
        if (out_hid)
            *(float4*)(out_hid + ((size_t)n * TSTEP + t) * 1024 + j) = hv;
    }
}

// ---------------------------------------------------------------------------
// Persistent decode kernel: all 63 steps, 6 grid barriers per step
// ---------------------------------------------------------------------------
__global__ void __launch_bounds__(128) decode_kernel(
        const float* __restrict__ dec_init,
        const float* __restrict__ W_att_dec,
        const float* __restrict__ W_hh,
        const float* __restrict__ W_ih,
        const float* __restrict__ b_ih,
        const float* __restrict__ b_hh,
        const float* __restrict__ v_att,
        float* __restrict__ out) {
    __shared__ float sm[11520];   // 46080 B
    int b = blockIdx.x;
    int tid = threadIdx.x;

    for (int i = b * 128 + tid; i < 2 * NB * HID; i += NBLK * 128)
        g_h[i] = dec_init[i];
    gridbar();

    for (int t = 0; t < TSTEP; t++) {
        // phase A: dp(32) + gh0(96) + gh1(96), split-K 4, KR=256
        if (b < 32) {
            int tile = b >> 2, split = b & 3;
            gemm_tc<8>(g_h + NB * HID, W_att_dec, 1024, tile * 128, split * 256,
                       g_dp_part + (size_t)split * NB * 1024, sm);
        } else if (b < 128) {
            int x = b - 32; int tile = x >> 2, split = x & 3;
            gemm_tc<8>(g_h, W_hh, G3, tile * 128, split * 256,
                       g_gh0_part + (size_t)split * NB * G3, sm);
        } else {
            int x = b - 128; int tile = x >> 2, split = x & 3;
            gemm_tc<8>(g_h + NB * HID, W_hh + (size_t)G3 * 1024, G3, tile * 128,
                       split * 256, g_gh1_part + (size_t)split * NB * G3, sm);
        }
        gridbar();

        // attention: score + softmax + merged (32 blocks)
        if (b < 32) attn_body(b, t, v_att, out, sm);
        gridbar();

        // gi layer 0: 24 tiles x 8 splits = 192 blocks, KR=128
        if (b < 192) {
            int tile = b >> 3, split = b & 7;
            gemm_tc<4>(g_merged, W_ih, G3, tile * 128, split * 128,
                       g_gi_part + (size_t)split * NB * G3, sm);
        }
        gridbar();

        // combine layer 0
        if (b < 32) combine_body(0, t, b, b_ih, b_hh, nullptr);
        gridbar();

        // gi layer 1
        if (b < 192) {
            int tile = b >> 3, split = b & 7;
            gemm_tc<4>(g_h, W_ih + (size_t)G3 * 1024, G3, tile * 128, split * 128,
                       g_gi_part + (size_t)split * NB * G3, sm);
        }
        gridbar();

        // combine layer 1 (+ dec_hids output)
        if (b < 32) combine_body(1, t, b, b_ih + G3, b_hh + G3, out);
        gridbar();
    }

    for (int i = b * 128 + tid; i < 2 * NB * HID; i += NBLK * 128)
        out[DECPREV_BASE + i] = g_h[i];
}

// ---------------------------------------------------------------------------
// Prologue: 3 fused fp32 GEMMs (enc_proj, emb_merged, encW) + barrier reset
// ---------------------------------------------------------------------------
__global__ void prol_gemm_kernel(const float* __restrict__ enc_hids,
                                 const int*   __restrict__ input_ids,
                                 const float* __restrict__ emb_table,
                                 const float* __restrict__ b_in,
                                 const float* __restrict__ b_ctx,
                                 const float* __restrict__ W_att_enc,
                                 const float* __restrict__ W_in,
                                 const float* __restrict__ W_ctx) {
    if (blockIdx.x == 0 && threadIdx.x == 0) {
        g_bar_cnt = 0;
        g_bar_gen = 0;
    }
    __shared__ float As[2][32 * 68];
    __shared__ float Ws[2][32 * 68];
    int mode = blockIdx.x >> 9;
    int b = blockIdx.x & 511;
    int rt = b >> 4, ct = b & 15;
    int r0 = rt * 64, c0 = ct * 64;
    int tid = threadIdx.x;
    int lp = tid & 7, lr = tid >> 3;
    int tx = tid & 15, ty = tid >> 4;
    int rows = (mode == 1) ? (TSTEP * NB) : 2048;
    const float* W = (mode == 0) ? W_att_enc : ((mode == 1) ? W_in : W_ctx);

    float4 a[2], wv[2];
#define PROL_FETCH(k0)                                                          \
    {                                                                           \
        _Pragma("unroll")                                                       \
        for (int h = 0; h < 2; h++) {                                           \
            int gr = r0 + lr + h * 32;                                          \
            if (mode != 1) {                                                    \
                a[h] = *(const float4*)(enc_hids + (size_t)gr * 1024 + (k0) + lp * 4); \
            } else if (gr < rows) {                                             \
                int id = input_ids[(gr & 31) * 64 + (gr >> 5)];                 \
                a[h] = *(const float4*)(emb_table + (size_t)id * 1024 + (k0) + lp * 4); \
            } else {                                                            \
                a[h] = make_float4(0.f, 0.f, 0.f, 0.f);                         \
            }                                                                   \
            wv[h] = *(const float4*)(W + (size_t)(c0 + lr + h * 32) * 1024 + (k0) + lp * 4); \
        }                                                                       \
    }
#define PROL_STORE(buf)                                                         \
    {                                                                           \
        _Pragma("unroll")                                                       \
        for (int h = 0; h < 2; h++) {                                           \
            int rr = lr + h * 32;                                               \
            As[buf][(lp * 4 + 0) * 68 + rr] = a[h].x;                           \
            As[buf][(lp * 4 + 1) * 68 + rr] = a[h].y;                           \
            As[buf][(lp * 4 + 2) * 68 + rr] = a[h].z;                           \
            As[buf][(lp * 4 + 3) * 68 + rr] = a[h].w;                           \
            Ws[buf][(lp * 4 + 0) * 68 + rr] = wv[h].x;                          \
            Ws[buf][(lp * 4 + 1) * 68 + rr] = wv[h].y;                          \
            Ws[buf][(lp * 4 + 2) * 68 + rr] = wv[h].z;                          \
            Ws[buf][(lp * 4 + 3) * 68 + rr] = wv[h].w;                          \
        }                                                                       \
    }

    float acc[4][4];
#pragma unroll
    for (int i = 0; i < 4; i++)
#pragma unroll
        for (int j = 0; j < 4; j++) acc[i][j] = 0.f;

    PROL_FETCH(0);
    PROL_STORE(0);
    __syncthreads();
    for (int c = 0; c < 32; c++) {
        const float* as = As[c & 1];
        const float* ws = Ws[c & 1];
        if (c + 1 < 32) PROL_FETCH((c + 1) * 32);
#pragma unroll
        for (int kk = 0; kk < 32; kk++) {
            float4 a4 = *(const float4*)&as[kk * 68 + ty * 4];
            float4 b4 = *(const float4*)&ws[kk * 68 + tx * 4];
            float avv[4] = {a4.x, a4.y, a4.z, a4.w};
            float bvv[4] = {b4.x, b4.y, b4.z, b4.w};
#pragma unroll
            for (int i = 0; i < 4; i++)
#pragma unroll
                for (int j = 0; j < 4; j++) acc[i][j] += avv[i] * bvv[j];
        }
        if (c + 1 < 32) {
            PROL_STORE((c + 1) & 1);
            __syncthreads();
        }
    }
    float* outb = (mode == 0) ? g_enc_proj : ((mode == 1) ? g_emb_merged : g_encW);
#pragma unroll
    for (int i = 0; i < 4; i++) {
        int rr = r0 + ty * 4 + i;
        if (rr >= rows) continue;
#pragma unroll
        for (int j = 0; j < 4; j++) {
            int cc = c0 + tx * 4 + j;
            float bias = (mode == 1) ? (b_in[cc] + b_ctx[cc]) : 0.f;
            outb[(size_t)rr * 1024 + cc] = acc[i][j] + bias;
        }
    }
#undef PROL_FETCH
#undef PROL_STORE
}

// ---------------------------------------------------------------------------
extern "C" void kernel_launch(void* const* d_in, const int* in_sizes, int n_in,
                              void* d_out, int out_size) {
    const int*   input_ids = (const int*)  d_in[0];
    const float* dec_init  = (const float*)d_in[1];
    const float* enc_hids  = (const float*)d_in[2];
    const float* emb_table = (const float*)d_in[3];
    const float* W_in      = (const float*)d_in[4];
    const float* b_in      = (const float*)d_in[5];
    const float* W_ctx     = (const float*)d_in[6];
    const float* b_ctx     = (const float*)d_in[7];
    const float* W_att_dec = (const float*)d_in[8];
    const float* W_att_enc = (const float*)d_in[9];
    const float* v_att     = (const float*)d_in[10];
    const float* W_ih      = (const float*)d_in[11];
    const float* W_hh      = (const float*)d_in[12];
    const float* b_ih      = (const float*)d_in[13];
    const float* b_hh      = (const float*)d_in[14];
    float* out = (float*)d_out;

    prol_gemm_kernel<<<1536, 256>>>(enc_hids, input_ids, emb_table,
                                    b_in, b_ctx, W_att_enc, W_in, W_ctx);
    decode_kernel<<<NBLK, 128>>>(dec_init, W_att_dec, W_hh, W_ih,
                                 b_ih, b_hh, v_att, out);
}